// round 5
// baseline (speedup 1.0000x reference)
#include <cuda_runtime.h>
#include <cstdint>

// Problem constants (fixed shapes).
#define R_DIM 64
#define I_DIM 256
#define O_DIM 256
#define TE_BLK 32          // entity rows per block (16 row-pairs)
#define P_DIM  16          // row-pairs per block
#define MAIN_THREADS 128   // thread owns 2 adjacent output cols for all 32 rows
#define I_SPLIT 16         // wsum parallel split over i

// Scratch (static __device__ — no allocs).
__device__ unsigned long long g_wdup[R_DIM * O_DIM];   // {w,w} per (r,o), 128KB
__device__ float g_wpart[I_SPLIT][R_DIM * O_DIM];      // 1MB partials

__device__ __forceinline__ unsigned long long ffma2(unsigned long long a,
                                                    unsigned long long b,
                                                    unsigned long long c) {
    unsigned long long d;
    asm("fma.rn.f32x2 %0, %1, %2, %3;" : "=l"(d) : "l"(a), "l"(b), "l"(c));
    return d;
}
__device__ __forceinline__ unsigned long long pack2(float lo, float hi) {
    unsigned long long v;
    asm("mov.b64 %0, {%1, %2};" : "=l"(v) : "f"(lo), "f"(hi));
    return v;
}
__device__ __forceinline__ void unpack2(unsigned long long v, float& lo, float& hi) {
    asm("mov.b64 {%0, %1}, %2;" : "=f"(lo), "=f"(hi) : "l"(v));
}

// ---------------------------------------------------------------------------
// Kernel 1a: partial W sums. grid(64, I_SPLIT), block(256).
// ---------------------------------------------------------------------------
__global__ void wsum_part_kernel(const float* __restrict__ W) {
    const int r  = blockIdx.x;
    const int iy = blockIdx.y;
    const int o  = threadIdx.x;
    const float* base = W + (size_t)r * I_DIM * O_DIM
                          + (size_t)iy * (I_DIM / I_SPLIT) * O_DIM + o;
    float s = 0.f;
#pragma unroll
    for (int i = 0; i < I_DIM / I_SPLIT; i++) s += base[(size_t)i * O_DIM];
    g_wpart[iy][r * O_DIM + o] = s;
}

// Kernel 1b: reduce partials, write duplicated-packed W_sum. grid(64), block(256).
__global__ void wsum_fin_kernel() {
    const int r = blockIdx.x;
    const int o = threadIdx.x;
    float s = 0.f;
#pragma unroll
    for (int iy = 0; iy < I_SPLIT; iy++) s += g_wpart[iy][r * O_DIM + o];
    g_wdup[r * O_DIM + o] = pack2(s, s);
}

// ---------------------------------------------------------------------------
// Kernel 2 (fused main). Block tile: 32 rows x 256 cols, 128 threads.
// acc[p] pair (packed f32x2) = {out[2p][c], out[2p+1][c]} for thread cols
// c0=2*tid, c1=2*tid+1.
// Per r per thread: 1 LDG.128 (dup w for 2 cols) + 8 broadcast LDS.128
// + 32 FFMA2  ->  FMA-limited (64 FMA-cyc vs 48 L1-wf per block per r).
// ---------------------------------------------------------------------------
__global__ __launch_bounds__(MAIN_THREADS, 5)
void rgcn_main_kernel(const float* __restrict__ x,
                      const float* __restrict__ cs,
                      float* __restrict__ out,
                      int E) {
    __shared__ float xs[TE_BLK];
    __shared__ __align__(16) unsigned long long csrp[R_DIM * P_DIM]; // [r][p], 8KB

    const int tid  = threadIdx.x;
    const int e0   = blockIdx.x * TE_BLK;
    const int warp = tid >> 5;
    const int lane = tid & 31;

    // --- Phase B: x row sums; warp w handles rows 8w..8w+7 ---
#pragma unroll
    for (int k = 0; k < TE_BLK / 4; k++) {
        const int t = warp * (TE_BLK / 4) + k;
        const int e = e0 + t;
        float s = 0.f;
        if (e < E) {
            const float4* row = reinterpret_cast<const float4*>(x + (size_t)e * I_DIM);
            float4 a = row[lane];
            float4 b = row[lane + 32];
            s = (a.x + a.y) + (a.z + a.w) + (b.x + b.y) + (b.z + b.w);
        }
#pragma unroll
        for (int off = 16; off > 0; off >>= 1)
            s += __shfl_xor_sync(0xffffffffu, s, off);
        if (lane == 0) xs[t] = s;
    }
    __syncthreads();

    // --- Phase C: csrp[r][p] = {xs[2p]/cs[e0+2p][r], xs[2p+1]/cs[e0+2p+1][r]} ---
#pragma unroll
    for (int k = 0; k < (R_DIM * P_DIM) / MAIN_THREADS; k++) {
        const int idx = k * MAIN_THREADS + tid;
        const int r = idx >> 4;              // / P_DIM
        const int p = idx & (P_DIM - 1);
        const int ea = e0 + 2 * p;
        const int eb = ea + 1;
        float va = 0.f, vb = 0.f;
        if (ea < E) va = __fdividef(xs[2 * p],     cs[(size_t)ea * R_DIM + r]);
        if (eb < E) vb = __fdividef(xs[2 * p + 1], cs[(size_t)eb * R_DIM + r]);
        csrp[idx] = pack2(va, vb);
    }
    __syncthreads();

    // --- Phase D: FFMA2 mainloop ---
    unsigned long long acc0[P_DIM], acc1[P_DIM];
#pragma unroll
    for (int p = 0; p < P_DIM; p++) { acc0[p] = 0ull; acc1[p] = 0ull; }

    const ulonglong2* wdup2 = reinterpret_cast<const ulonglong2*>(g_wdup); // [r][c/2]

#pragma unroll 2
    for (int r = 0; r < R_DIM; r++) {
        // This thread's two duplicated W columns for relation r (LDG.128, L1-hot).
        ulonglong2 w = wdup2[r * (O_DIM / 2) + tid];
        const ulonglong2* c8 = reinterpret_cast<const ulonglong2*>(&csrp[r * P_DIM]);
#pragma unroll
        for (int q = 0; q < P_DIM / 2; q++) {          // 8 broadcast LDS.128
            ulonglong2 c = c8[q];
            acc0[2 * q]     = ffma2(w.x, c.x, acc0[2 * q]);
            acc1[2 * q]     = ffma2(w.y, c.x, acc1[2 * q]);
            acc0[2 * q + 1] = ffma2(w.x, c.y, acc0[2 * q + 1]);
            acc1[2 * q + 1] = ffma2(w.y, c.y, acc1[2 * q + 1]);
        }
    }

    // --- Epilogue: two coalesced float2 stores per row-pair ---
    float2* out2 = reinterpret_cast<float2*>(out);
#pragma unroll
    for (int p = 0; p < P_DIM; p++) {
        const int ea = e0 + 2 * p;
        const int eb = ea + 1;
        float a_lo, a_hi, b_lo, b_hi;
        unpack2(acc0[p], a_lo, a_hi);   // rows 2p / 2p+1, col c0
        unpack2(acc1[p], b_lo, b_hi);   // rows 2p / 2p+1, col c1
        if (ea < E) out2[(size_t)ea * (O_DIM / 2) + tid] = make_float2(a_lo, b_lo);
        if (eb < E) out2[(size_t)eb * (O_DIM / 2) + tid] = make_float2(a_hi, b_hi);
    }
}

// ---------------------------------------------------------------------------
// Launch. Inputs: x (E*256 f32), cs (E*64 f32), W (64*256*256 f32),
// edge_index (unused by the factorized math). Output: E*256 f32.
// ---------------------------------------------------------------------------
extern "C" void kernel_launch(void* const* d_in, const int* in_sizes, int n_in,
                              void* d_out, int out_size) {
    const float* x  = (const float*)d_in[0];
    const float* cs = (const float*)d_in[1];
    const float* W  = (const float*)d_in[2];
    float* out = (float*)d_out;

    const int E = in_sizes[0] / I_DIM;

    wsum_part_kernel<<<dim3(R_DIM, I_SPLIT), O_DIM>>>(W);
    wsum_fin_kernel<<<R_DIM, O_DIM>>>();
    const int grid = (E + TE_BLK - 1) / TE_BLK;
    rgcn_main_kernel<<<grid, MAIN_THREADS>>>(x, cs, out, E);
}

// round 6
// speedup vs baseline: 1.9116x; 1.9116x over previous
#include <cuda_runtime.h>
#include <cstdint>

// Problem constants (fixed shapes).
#define R_DIM 64
#define I_DIM 256
#define O_DIM 256
#define TE_BLK 16          // entity rows per block (8 row-pairs) — known-safe regs
#define P_DIM  8           // row-pairs per block
#define MAIN_THREADS 128   // thread owns 2 adjacent output cols for 16 rows
#define I_SPLIT 16         // wsum parallel split over i

// Scratch (static __device__ — no allocs).
__device__ float g_wsum[R_DIM * O_DIM];            // plain W_sum, 64KB (L1/L2-hot)
__device__ float g_wpart[I_SPLIT][R_DIM * O_DIM];  // partials

__device__ __forceinline__ unsigned long long ffma2(unsigned long long a,
                                                    unsigned long long b,
                                                    unsigned long long c) {
    unsigned long long d;
    asm("fma.rn.f32x2 %0, %1, %2, %3;" : "=l"(d) : "l"(a), "l"(b), "l"(c));
    return d;
}
__device__ __forceinline__ unsigned long long pack2(float lo, float hi) {
    unsigned long long v;
    asm("mov.b64 %0, {%1, %2};" : "=l"(v) : "f"(lo), "f"(hi));
    return v;
}
__device__ __forceinline__ void unpack2(unsigned long long v, float& lo, float& hi) {
    asm("mov.b64 {%0, %1}, %2;" : "=f"(lo), "=f"(hi) : "l"(v));
}

// ---------------------------------------------------------------------------
// Kernel 1a: partial W sums. grid(64, I_SPLIT), block(256).
// ---------------------------------------------------------------------------
__global__ void wsum_part_kernel(const float* __restrict__ W) {
    const int r  = blockIdx.x;
    const int iy = blockIdx.y;
    const int o  = threadIdx.x;
    const float* base = W + (size_t)r * I_DIM * O_DIM
                          + (size_t)iy * (I_DIM / I_SPLIT) * O_DIM + o;
    float s = 0.f;
#pragma unroll
    for (int i = 0; i < I_DIM / I_SPLIT; i++) s += base[(size_t)i * O_DIM];
    g_wpart[iy][r * O_DIM + o] = s;
}

// Kernel 1b: reduce partials. grid(64), block(256).
__global__ void wsum_fin_kernel() {
    const int r = blockIdx.x;
    const int o = threadIdx.x;
    float s = 0.f;
#pragma unroll
    for (int iy = 0; iy < I_SPLIT; iy++) s += g_wpart[iy][r * O_DIM + o];
    g_wsum[r * O_DIM + o] = s;
}

// ---------------------------------------------------------------------------
// Kernel 2 (fused main). Block tile: 16 rows x 256 cols, 128 threads.
// acc[p] pair (packed f32x2) = {out[2p][c], out[2p+1][c]} for thread cols
// c0=2*tid, c1=2*tid+1.
// Per r per thread: 1 LDG.64 (plain w, 2 cols) + 2 reg-dups (ALU) +
// 4 broadcast LDS.128 + 16 FFMA2.
// Per block per r: 24 L1 wavefronts vs 32 FMA-cycles -> FMA-led.
// ---------------------------------------------------------------------------
__global__ __launch_bounds__(MAIN_THREADS, 6)
void rgcn_main_kernel(const float* __restrict__ x,
                      const float* __restrict__ cs,
                      float* __restrict__ out,
                      int E) {
    __shared__ float xs[TE_BLK];
    __shared__ __align__(16) unsigned long long csrp[R_DIM * P_DIM]; // [r][p], 4KB

    const int tid  = threadIdx.x;
    const int e0   = blockIdx.x * TE_BLK;
    const int warp = tid >> 5;
    const int lane = tid & 31;

    // --- Phase B: x row sums; warp w handles rows 4w..4w+3 ---
#pragma unroll
    for (int k = 0; k < TE_BLK / 4; k++) {
        const int t = warp * (TE_BLK / 4) + k;
        const int e = e0 + t;
        float s = 0.f;
        if (e < E) {
            const float4* row = reinterpret_cast<const float4*>(x + (size_t)e * I_DIM);
            float4 a = row[lane];
            float4 b = row[lane + 32];
            s = (a.x + a.y) + (a.z + a.w) + (b.x + b.y) + (b.z + b.w);
        }
#pragma unroll
        for (int off = 16; off > 0; off >>= 1)
            s += __shfl_xor_sync(0xffffffffu, s, off);
        if (lane == 0) xs[t] = s;
    }
    __syncthreads();

    // --- Phase C: csrp[r][p] = {xs[2p]/cs[e0+2p][r], xs[2p+1]/cs[e0+2p+1][r]} ---
#pragma unroll
    for (int k = 0; k < (R_DIM * P_DIM) / MAIN_THREADS; k++) {
        const int idx = k * MAIN_THREADS + tid;
        const int r = idx >> 3;              // / P_DIM
        const int p = idx & (P_DIM - 1);
        const int ea = e0 + 2 * p;
        const int eb = ea + 1;
        float va = 0.f, vb = 0.f;
        if (ea < E) va = __fdividef(xs[2 * p],     cs[(size_t)ea * R_DIM + r]);
        if (eb < E) vb = __fdividef(xs[2 * p + 1], cs[(size_t)eb * R_DIM + r]);
        csrp[idx] = pack2(va, vb);
    }
    __syncthreads();

    // --- Phase D: FFMA2 mainloop ---
    unsigned long long acc0[P_DIM], acc1[P_DIM];
#pragma unroll
    for (int p = 0; p < P_DIM; p++) { acc0[p] = 0ull; acc1[p] = 0ull; }

    const float2* wsum2 = reinterpret_cast<const float2*>(g_wsum);   // [r][c/2]

#pragma unroll 2
    for (int r = 0; r < R_DIM; r++) {
        // Plain w for this thread's two columns (LDG.64, L1-hot), dup in regs.
        float2 wv = wsum2[r * (O_DIM / 2) + tid];
        unsigned long long wx = pack2(wv.x, wv.x);   // ALU mov, not FMA pipe
        unsigned long long wy = pack2(wv.y, wv.y);

        const ulonglong2* c4 = reinterpret_cast<const ulonglong2*>(&csrp[r * P_DIM]);
#pragma unroll
        for (int q = 0; q < P_DIM / 2; q++) {        // 4 broadcast LDS.128
            ulonglong2 c = c4[q];
            acc0[2 * q]     = ffma2(wx, c.x, acc0[2 * q]);
            acc1[2 * q]     = ffma2(wy, c.x, acc1[2 * q]);
            acc0[2 * q + 1] = ffma2(wx, c.y, acc0[2 * q + 1]);
            acc1[2 * q + 1] = ffma2(wy, c.y, acc1[2 * q + 1]);
        }
    }

    // --- Epilogue: two coalesced float2 stores per row-pair ---
    float2* out2 = reinterpret_cast<float2*>(out);
#pragma unroll
    for (int p = 0; p < P_DIM; p++) {
        const int ea = e0 + 2 * p;
        const int eb = ea + 1;
        float a_lo, a_hi, b_lo, b_hi;
        unpack2(acc0[p], a_lo, a_hi);   // rows 2p / 2p+1, col c0
        unpack2(acc1[p], b_lo, b_hi);   // rows 2p / 2p+1, col c1
        if (ea < E) out2[(size_t)ea * (O_DIM / 2) + tid] = make_float2(a_lo, b_lo);
        if (eb < E) out2[(size_t)eb * (O_DIM / 2) + tid] = make_float2(a_hi, b_hi);
    }
}

// ---------------------------------------------------------------------------
// Launch. Inputs: x (E*256 f32), cs (E*64 f32), W (64*256*256 f32),
// edge_index (unused by the factorized math). Output: E*256 f32.
// ---------------------------------------------------------------------------
extern "C" void kernel_launch(void* const* d_in, const int* in_sizes, int n_in,
                              void* d_out, int out_size) {
    const float* x  = (const float*)d_in[0];
    const float* cs = (const float*)d_in[1];
    const float* W  = (const float*)d_in[2];
    float* out = (float*)d_out;

    const int E = in_sizes[0] / I_DIM;

    wsum_part_kernel<<<dim3(R_DIM, I_SPLIT), O_DIM>>>(W);
    wsum_fin_kernel<<<R_DIM, O_DIM>>>();
    const int grid = (E + TE_BLK - 1) / TE_BLK;
    rgcn_main_kernel<<<grid, MAIN_THREADS>>>(x, cs, out, E);
}